// round 7
// baseline (speedup 1.0000x reference)
#include <cuda_runtime.h>

// EfficientAttention fused kernel (sm_100a).
// R7: T=4 conv (4 adjacent j per thread, 8 channels) inside the occ-2
// half-row frame. Conv LDS/thread 304 -> 168 for identical fma2 count.
// 16 channel-groups folded to 8 W4 groups via two-pass smem RMW.
// K-load indexing reduced to shifts (320 % 10 == 0 -> m loop-invariant).

#define NTHR  320
#define QROW2 89           // logical j in [base-4, base+85); odd => conflict-free
#define KROW  52
#define W_OFF1   5242880   // 4*128*160*64
#define W_OFF2   6062080   // W_OFF1 + 512*160*10

__device__ __forceinline__ unsigned long long pack2(float lo, float hi) {
    unsigned long long r;
    asm("mov.b64 %0, {%1, %2};" : "=l"(r) : "f"(lo), "f"(hi));
    return r;
}
__device__ __forceinline__ void unpack2(unsigned long long v, float& lo, float& hi) {
    asm("mov.b64 {%0, %1}, %2;" : "=f"(lo), "=f"(hi) : "l"(v));
}
__device__ __forceinline__ void fma2(unsigned long long& d, unsigned long long a,
                                     unsigned long long b) {
    asm("fma.rn.f32x2 %0, %1, %2, %3;" : "=l"(d) : "l"(a), "l"(b), "l"(d));
}

__device__ __forceinline__ float getQ(const float* colbase_s, const float* row_g,
                                      int k, int jlog, int loJ) {
    if ((unsigned)(jlog - loJ) < (unsigned)QROW2)
        return colbase_s[jlog - loJ];
    return row_g[jlog * 64 + k];
}

__global__ void __launch_bounds__(NTHR, 2)
ea_kernel(const float* __restrict__ gL, const float* __restrict__ gR,
          const float* __restrict__ gK, const float* __restrict__ gBias,
          const float* __restrict__ gGamma, const float* __restrict__ gBeta,
          const float* __restrict__ gMean, const float* __restrict__ gVar,
          float* __restrict__ out)
{
    extern __shared__ float sm[];
    float* Qt = sm;                        // 128*89 (L ch 0..63, R ch 64..127)
    float* Kc = Qt + 128 * QROW2;          // 128*52:  Kc[c][w*10+m]
    float* W4 = Kc + 128 * KROW;           // 8*80*11: logit partials
    float* WS = W4 + 8 * 80 * 11;          // 80*12:   softmaxed weights

    const int t    = threadIdx.x;
    const int row  = blockIdx.x >> 1;
    const int h    = blockIdx.x & 1;
    const int base = h * 80;
    const int loJ  = base - 4;

    const float* Lrow = gL + (size_t)row * (160 * 64);
    const float* Rrow = gR + (size_t)row * (160 * 64);

    // ---- zero SAME-conv padding cols ----
    {
        const int npad = h ? 5 : 4;        // h=0: cols 0..3 ; h=1: cols 84..88
        const int pad0 = h ? 84 : 0;
        for (int z = t; z < 128 * 5; z += NTHR) {
            int c = z / 5, pc = z % 5;
            if (pc < npad) Qt[c * QROW2 + pad0 + pc] = 0.f;
        }
    }

    // ---- load valid j range (coalesced float4) -> transposed smem ----
    {
        const int jv0 = h ? 76 : 0;
        const int nv  = h ? 84 : 85;
        const int n4  = nv * 16;
        for (int i4 = t; i4 < n4; i4 += NTHR) {
            int jrel = i4 >> 4, c = (i4 & 15) << 2;
            int col  = (jv0 + jrel) - loJ;
            int gidx = jv0 * 16 + i4;
            float4 v = reinterpret_cast<const float4*>(Lrow)[gidx];
            Qt[(c + 0) * QROW2 + col] = v.x;
            Qt[(c + 1) * QROW2 + col] = v.y;
            Qt[(c + 2) * QROW2 + col] = v.z;
            Qt[(c + 3) * QROW2 + col] = v.w;
            float4 u = reinterpret_cast<const float4*>(Rrow)[gidx];
            Qt[(c + 64) * QROW2 + col] = u.x;
            Qt[(c + 65) * QROW2 + col] = u.y;
            Qt[(c + 66) * QROW2 + col] = u.z;
            Qt[(c + 67) * QROW2 + col] = u.w;
        }
    }

    // ---- load conv kernel: shifts-only indexing (320 % 10 == 0) ----
    {
        const int m0 = t % 10;             // one div, loop-invariant
        const int q0 = t / 10;
        #pragma unroll
        for (int kk = 0; kk < 20; kk++) {
            int qq = q0 + kk * 32;
            int c  = qq & 127;
            int w  = qq >> 7;
            Kc[c * KROW + w * 10 + m0] = gK[t + kk * NTHR];
        }
    }
    __syncthreads();

    // ---- conv: thread = (c-group of 8 ch, j-quad) ----
    const int jq = t % 20;                 // local j = 4jq .. 4jq+3
    const int cg = t / 20;                 // 0..15
    {
        unsigned long long acc[4][5];
        #pragma unroll
        for (int j = 0; j < 4; j++)
            #pragma unroll
            for (int p = 0; p < 5; p++) acc[j][p] = 0ull;

        // window col for local jA=4jq: (base+4jq-2) - loJ = 4jq+2
        const float* qbase = Qt + (cg * 8) * QROW2 + 4 * jq + 2;
        const float* kbase = Kc + (cg * 8) * KROW;

        #pragma unroll 2
        for (int ci = 0; ci < 8; ci++) {
            const float* q = qbase + ci * QROW2;
            unsigned long long pk[8];
            #pragma unroll
            for (int w = 0; w < 8; w++) pk[w] = pack2(q[w], q[w]);

            const float* krow = kbase + ci * KROW;
            const ulonglong2* kp = reinterpret_cast<const ulonglong2*>(krow);
            #pragma unroll
            for (int i = 0; i < 12; i++) {
                ulonglong2 kv = kp[i];
                const int pi0 = 2 * i, pi1 = 2 * i + 1;
                const int p0 = pi0 % 5, w0 = pi0 / 5;
                const int p1 = pi1 % 5, w1 = pi1 / 5;
                #pragma unroll
                for (int j = 0; j < 4; j++) {
                    fma2(acc[j][p0], pk[w0 + j], kv.x);
                    fma2(acc[j][p1], pk[w1 + j], kv.y);
                }
            }
            unsigned long long kl =
                reinterpret_cast<const unsigned long long*>(krow)[24]; // w=4,p=4
            #pragma unroll
            for (int j = 0; j < 4; j++)
                fma2(acc[j][4], pk[4 + j], kl);
        }

        // two-pass fold: cg 0-7 write, barrier, cg 8-15 accumulate in place
        if (cg < 8) {
            #pragma unroll
            for (int j = 0; j < 4; j++) {
                float* wd = W4 + (cg * 80 + 4 * jq + j) * 11;
                #pragma unroll
                for (int p = 0; p < 5; p++) {
                    float lo, hi;
                    unpack2(acc[j][p], lo, hi);
                    wd[2 * p] = lo; wd[2 * p + 1] = hi;
                }
            }
        }
        __syncthreads();
        if (cg >= 8) {
            #pragma unroll
            for (int j = 0; j < 4; j++) {
                float* wd = W4 + ((cg - 8) * 80 + 4 * jq + j) * 11;
                #pragma unroll
                for (int p = 0; p < 5; p++) {
                    float lo, hi;
                    unpack2(acc[j][p], lo, hi);
                    wd[2 * p]     += lo;
                    wd[2 * p + 1] += hi;
                }
            }
        }
    }
    __syncthreads();

    // ---- logit reduction + softmax + weight outputs (threads 0..79) ----
    if (t < 80) {
        float v[10];
        #pragma unroll
        for (int m = 0; m < 10; m++) {
            float a = gBias[m];
            #pragma unroll
            for (int g = 0; g < 8; g++)
                a += W4[(g * 80 + t) * 11 + m];
            v[m] = a;
        }
        float mx = v[0];
        #pragma unroll
        for (int m = 1; m < 10; m++) mx = fmaxf(mx, v[m]);
        float s = 0.f;
        #pragma unroll
        for (int m = 0; m < 10; m++) { float e = __expf(v[m] - mx); v[m] = e; s += e; }
        float inv = 1.f / s;
        float* wr = WS + t * 12;
        size_t wo = (size_t)row * 1600 + (size_t)(base + t) * 10;
        #pragma unroll
        for (int m = 0; m < 10; m++) {
            float wv = v[m] * inv;
            wr[m] = wv;
            out[W_OFF1 + wo + m] = wv;
            out[W_OFF2 + wo + m] = wv;
        }
    }
    __syncthreads();

    // ---- shiftmap gather + BN + tanh: thread = (k, group of 16 j) ----
    {
        const int k  = t & 63;
        const int g  = t >> 6;             // 0..4
        const int j0 = base + g * 16;

        float sc = gGamma[k] / sqrtf(gVar[k] + 1e-3f);
        float sh = gBeta[k] - gMean[k] * sc;

        const float* Lc = Qt + k * QROW2;
        const float* Rc = Qt + (64 + k) * QROW2;

        float lw[5], rw[5];
        #pragma unroll
        for (int s = 0; s < 5; s++) {
            int li = j0 - s; if (li < 0) li += 160;
            lw[s] = getQ(Lc, Lrow, k, li, loJ);
            rw[s] = getQ(Rc, Rrow, k, j0 + s, loJ);
        }

        float* xout = out + (size_t)(row * 160 + j0) * 64 + k;
        #pragma unroll
        for (int jj = 0; jj < 16; jj++) {
            int j = j0 + jj;
            const unsigned long long* wp =
                reinterpret_cast<const unsigned long long*>(WS + (j - base) * 12);
            unsigned long long a = 0ull;
            #pragma unroll
            for (int s = 0; s < 5; s++)
                fma2(a, wp[s], pack2(lw[s], rw[s]));
            float lo, hi;
            unpack2(a, lo, hi);
            float x = (lo + hi) * sc + sh;
            float e = __expf(2.f * x);     // tanh = 1 - 2/(e^{2x}+1)
            x = 1.f - 2.f / (e + 1.f);
            xout[(size_t)jj * 64] = x;

            int ln = j + 1; if (ln >= 160) ln -= 160;
            int rn = j + 5; if (rn >= 160) rn -= 160;
            lw[4] = lw[3]; lw[3] = lw[2]; lw[2] = lw[1]; lw[1] = lw[0];
            lw[0] = getQ(Lc, Lrow, k, ln, loJ);
            rw[0] = rw[1]; rw[1] = rw[2]; rw[2] = rw[3]; rw[3] = rw[4];
            rw[4] = getQ(Rc, Rrow, k, rn, loJ);
        }
    }
}

extern "C" void kernel_launch(void* const* d_in, const int* in_sizes, int n_in,
                              void* d_out, int out_size)
{
    const float* L     = (const float*)d_in[0];
    const float* R     = (const float*)d_in[1];
    const float* K     = (const float*)d_in[2];
    const float* bias  = (const float*)d_in[3];
    const float* gamma = (const float*)d_in[4];
    const float* beta  = (const float*)d_in[5];
    const float* mean  = (const float*)d_in[6];
    const float* var   = (const float*)d_in[7];
    float* out = (float*)d_out;

    const int smem = (128 * QROW2 + 128 * KROW + 8 * 80 * 11 + 80 * 12) * 4; // 104192 B
    cudaFuncSetAttribute(ea_kernel, cudaFuncAttributeMaxDynamicSharedMemorySize, smem);
    ea_kernel<<<1024, NTHR, smem>>>(L, R, K, bias, gamma, beta, mean, var, out);
}